// round 1
// baseline (speedup 1.0000x reference)
#include <cuda_runtime.h>
#include <math.h>

#define NN 20000
#define EE 320000
#define DD 128
#define LL 3
#define BN_EPS 1e-5f

// ---------------- scratch (device globals; no allocation) ----------------
__device__ float g_h [NN*DD];
__device__ float g_e [EE*DD];
__device__ float g_et[EE*DD];   // edge temp: Ae, then Ae+Bh[src]+Ch[dst]
__device__ float g_Uh[NN*DD];
__device__ float g_Vh[NN*DD];
__device__ float g_Bh[NN*DD];
__device__ float g_Ch[NN*DD];
__device__ float g_agg[NN*DD];
__device__ float g_tmp[NN*DD];
__device__ float g_cnt[NN];
__device__ int   g_cnti[NN];
// stats: [0:128) sum_h, [128:256) sq_h, [256:384) sum_e, [384:512) sq_e
__device__ float g_stats[4*DD];
__device__ float g_scale[2*DD]; // [h | e]
__device__ float g_shift[2*DD];

// ---------------- helpers ----------------
__device__ __forceinline__ float sigm(float v){ return 1.f/(1.f+__expf(-v)); }
__device__ __forceinline__ float silu(float v){ return v*sigm(v); }

// ---------------- kernels ----------------
__global__ void k_zero_f(float* p, int n){
    int i = blockIdx.x*blockDim.x + threadIdx.x;
    if (i < n) p[i] = 0.f;
}
__global__ void k_zero_i(int* p, int n){
    int i = blockIdx.x*blockDim.x + threadIdx.x;
    if (i < n) p[i] = 0;
}
__global__ void k_count(const int* __restrict__ src){
    int i = blockIdx.x*blockDim.x + threadIdx.x;
    if (i < EE) atomicAdd(&g_cnti[src[i]], 1);
}
__global__ void k_cntf(){
    int i = blockIdx.x*blockDim.x + threadIdx.x;
    if (i < NN) g_cnt[i] = fmaxf((float)g_cnti[i], 1.f);
}

__global__ void k_init_h(const float* __restrict__ x,
                         const float* __restrict__ hw,
                         const float* __restrict__ hb){
    int n = blockIdx.x, d = threadIdx.x;
    float v = fmaf(x[n*2+0], hw[d], fmaf(x[n*2+1], hw[DD+d], hb[d]));
    g_h[n*DD+d] = silu(v);
}
__global__ void k_init_e(const float* __restrict__ ea,
                         const float* __restrict__ ew,
                         const float* __restrict__ eb){
    int e = blockIdx.x, d = threadIdx.x;
    float v = fmaf(ea[e], ew[d], eb[d]);
    g_e[e*DD+d] = silu(v);
}

// generic [rows,128] @ [128,128] + bias (optional silu). 128 threads, BR rows/block.
template<int BR, int ACT>
__global__ void k_gemm(const float* __restrict__ A, const float* __restrict__ W,
                       const float* __restrict__ bias, float* __restrict__ out, int rows){
    __shared__ float As[BR][DD];
    const int tid = threadIdx.x;
    const int row0 = blockIdx.x * BR;
    #pragma unroll
    for (int r = 0; r < BR; r++){
        int row = row0 + r;
        As[r][tid] = (row < rows) ? A[row*DD + tid] : 0.f;
    }
    __syncthreads();
    float acc[BR];
    #pragma unroll
    for (int r = 0; r < BR; r++) acc[r] = 0.f;
    #pragma unroll 4
    for (int k = 0; k < DD; k += 4){
        float w0 = W[(k+0)*DD + tid];
        float w1 = W[(k+1)*DD + tid];
        float w2 = W[(k+2)*DD + tid];
        float w3 = W[(k+3)*DD + tid];
        #pragma unroll
        for (int r = 0; r < BR; r++){
            float4 a = *reinterpret_cast<const float4*>(&As[r][k]);
            acc[r] = fmaf(a.x, w0, acc[r]);
            acc[r] = fmaf(a.y, w1, acc[r]);
            acc[r] = fmaf(a.z, w2, acc[r]);
            acc[r] = fmaf(a.w, w3, acc[r]);
        }
    }
    float b = bias[tid];
    #pragma unroll
    for (int r = 0; r < BR; r++){
        int row = row0 + r;
        if (row < rows){
            float v = acc[r] + b;
            if (ACT == 1) v = silu(v);
            out[row*DD + tid] = v;
        }
    }
}

// per-edge: msg scatter + edge-feature gather. 128 threads = features, 8 edges/block.
__global__ void k_edge(const int* __restrict__ src, const int* __restrict__ dst){
    const int tid = threadIdx.x;
    const int e0 = blockIdx.x * 8;
    #pragma unroll
    for (int i = 0; i < 8; i++){
        int eid = e0 + i;
        if (eid >= EE) break;
        int s = src[eid];
        int t = dst[eid];
        float ev  = g_e[eid*DD + tid];
        float msg = sigm(ev) * g_Vh[t*DD + tid];
        atomicAdd(&g_agg[s*DD + tid], msg);
        g_et[eid*DD + tid] += g_Bh[s*DD + tid] + g_Ch[t*DD + tid];
    }
}

__global__ void k_node_tmp(){
    int n = blockIdx.x, d = threadIdx.x;
    g_tmp[n*DD + d] = g_Uh[n*DD + d] + g_agg[n*DD + d] / g_cnt[n];
}

// column sums/sumsq partial reduce; thread = feature, R rows per block.
template<int R>
__global__ void k_colstats(const float* __restrict__ X, int rows,
                           float* __restrict__ sum, float* __restrict__ sumsq){
    const int d = threadIdx.x;
    const int r0 = blockIdx.x * R;
    const int r1 = min(rows, r0 + R);
    float s = 0.f, q = 0.f;
    for (int r = r0; r < r1; r++){
        float v = X[r*DD + d];
        s += v;
        q = fmaf(v, v, q);
    }
    atomicAdd(&sum[d], s);
    atomicAdd(&sumsq[d], q);
}

__global__ void k_bn_fin(const float* __restrict__ sum, const float* __restrict__ sumsq,
                         const float* __restrict__ gamma, const float* __restrict__ beta,
                         float rows, float* __restrict__ scale, float* __restrict__ shift){
    int d = threadIdx.x;
    float m   = sum[d] / rows;
    float var = sumsq[d] / rows - m*m;
    float inv = rsqrtf(var + BN_EPS);
    float sc  = inv * gamma[d];
    scale[d] = sc;
    shift[d] = beta[d] - m*sc;
}

// base += silu(X*scale + shift); thread = feature, block = row
__global__ void k_apply(float* __restrict__ base, const float* __restrict__ X,
                        const float* __restrict__ scale, const float* __restrict__ shift){
    int d = threadIdx.x;
    int idx = blockIdx.x*DD + d;
    float v = fmaf(X[idx], scale[d], shift[d]);
    base[idx] += silu(v);
}

// fused final MLP: silu(e@f1+b1) -> silu(@f2+b2) -> sigmoid(@f3+b3). 4 edges/block.
__global__ void k_final(const float* __restrict__ f1w, const float* __restrict__ f1b,
                        const float* __restrict__ f2w, const float* __restrict__ f2b,
                        const float* __restrict__ f3w, const float* __restrict__ f3b,
                        float* __restrict__ out){
    const int RB = 4;
    __shared__ float bufA[RB][DD];
    __shared__ float bufB[RB][DD];
    const int tid = threadIdx.x;
    const int e0 = blockIdx.x * RB;

    #pragma unroll
    for (int r = 0; r < RB; r++) bufA[r][tid] = g_e[(e0+r)*DD + tid];
    __syncthreads();

    // stage 1: bufA -> bufB
    {
        float acc[RB] = {0.f,0.f,0.f,0.f};
        #pragma unroll 4
        for (int k = 0; k < DD; k += 4){
            float w0 = f1w[(k+0)*DD + tid], w1 = f1w[(k+1)*DD + tid];
            float w2 = f1w[(k+2)*DD + tid], w3 = f1w[(k+3)*DD + tid];
            #pragma unroll
            for (int r = 0; r < RB; r++){
                float4 a = *reinterpret_cast<const float4*>(&bufA[r][k]);
                acc[r] = fmaf(a.x,w0, fmaf(a.y,w1, fmaf(a.z,w2, fmaf(a.w,w3, acc[r]))));
            }
        }
        float b = f1b[tid];
        #pragma unroll
        for (int r = 0; r < RB; r++) bufB[r][tid] = silu(acc[r] + b);
    }
    __syncthreads();

    // stage 2: bufB -> bufA
    {
        float acc[RB] = {0.f,0.f,0.f,0.f};
        #pragma unroll 4
        for (int k = 0; k < DD; k += 4){
            float w0 = f2w[(k+0)*DD + tid], w1 = f2w[(k+1)*DD + tid];
            float w2 = f2w[(k+2)*DD + tid], w3 = f2w[(k+3)*DD + tid];
            #pragma unroll
            for (int r = 0; r < RB; r++){
                float4 a = *reinterpret_cast<const float4*>(&bufB[r][k]);
                acc[r] = fmaf(a.x,w0, fmaf(a.y,w1, fmaf(a.z,w2, fmaf(a.w,w3, acc[r]))));
            }
        }
        float b = f2b[tid];
        #pragma unroll
        for (int r = 0; r < RB; r++) bufA[r][tid] = silu(acc[r] + b);
    }
    __syncthreads();

    // stage 3: partials into bufB, warp-per-row reduce
    float fw = f3w[tid];
    #pragma unroll
    for (int r = 0; r < RB; r++) bufB[r][tid] = bufA[r][tid] * fw;
    __syncthreads();

    int w = tid >> 5, lane = tid & 31;
    float v = bufB[w][lane] + bufB[w][lane+32] + bufB[w][lane+64] + bufB[w][lane+96];
    #pragma unroll
    for (int off = 16; off > 0; off >>= 1)
        v += __shfl_down_sync(0xffffffff, v, off);
    if (lane == 0) out[e0 + w] = sigm(v + f3b[0]);
}

// ---------------- host orchestration ----------------
extern "C" void kernel_launch(void* const* d_in, const int* in_sizes, int n_in,
                              void* d_out, int out_size){
    const float* x    = (const float*)d_in[0];
    const float* ea   = (const float*)d_in[1];
    const int*   eidx = (const int*)  d_in[2];
    const float* hp_w = (const float*)d_in[3];
    const float* hp_b = (const float*)d_in[4];
    const float* ep_w = (const float*)d_in[5];
    const float* ep_b = (const float*)d_in[6];
    const float* Uw   = (const float*)d_in[7];
    const float* Ub   = (const float*)d_in[8];
    const float* Vw   = (const float*)d_in[9];
    const float* Vb   = (const float*)d_in[10];
    const float* Aw   = (const float*)d_in[11];
    const float* Ab   = (const float*)d_in[12];
    const float* Bw   = (const float*)d_in[13];
    const float* Bb   = (const float*)d_in[14];
    const float* Cw   = (const float*)d_in[15];
    const float* Cb   = (const float*)d_in[16];
    const float* h_g  = (const float*)d_in[17];
    const float* h_bt = (const float*)d_in[18];
    const float* e_g  = (const float*)d_in[19];
    const float* e_bt = (const float*)d_in[20];
    const float* f1w  = (const float*)d_in[21];
    const float* f1b  = (const float*)d_in[22];
    const float* f2w  = (const float*)d_in[23];
    const float* f2b  = (const float*)d_in[24];
    const float* f3w  = (const float*)d_in[25];
    const float* f3b  = (const float*)d_in[26];
    float* out = (float*)d_out;

    const int* src = eidx;        // edge_index[0]: scatter target
    const int* dst = eidx + EE;   // edge_index[1]: gather source

    void* p;
    cudaGetSymbolAddress(&p, g_h);    float* ph    = (float*)p;
    cudaGetSymbolAddress(&p, g_e);    float* pe    = (float*)p;
    cudaGetSymbolAddress(&p, g_et);   float* pet   = (float*)p;
    cudaGetSymbolAddress(&p, g_Uh);   float* pUh   = (float*)p;
    cudaGetSymbolAddress(&p, g_Vh);   float* pVh   = (float*)p;
    cudaGetSymbolAddress(&p, g_Bh);   float* pBh   = (float*)p;
    cudaGetSymbolAddress(&p, g_Ch);   float* pCh   = (float*)p;
    cudaGetSymbolAddress(&p, g_agg);  float* pagg  = (float*)p;
    cudaGetSymbolAddress(&p, g_tmp);  float* ptmp  = (float*)p;
    cudaGetSymbolAddress(&p, g_cnti); int*   pcnti = (int*)p;
    cudaGetSymbolAddress(&p, g_stats);float* pst   = (float*)p;
    cudaGetSymbolAddress(&p, g_scale);float* psc   = (float*)p;
    cudaGetSymbolAddress(&p, g_shift);float* psh   = (float*)p;

    // input projections
    k_init_h<<<NN, DD>>>(x, hp_w, hp_b);
    k_init_e<<<EE, DD>>>(ea, ep_w, ep_b);

    // per-node counts
    k_zero_i<<<(NN+255)/256, 256>>>(pcnti, NN);
    k_count<<<(EE+255)/256, 256>>>(src);
    k_cntf<<<(NN+255)/256, 256>>>();

    for (int l = 0; l < LL; l++){
        const float* uw = Uw + l*DD*DD; const float* ub = Ub + l*DD;
        const float* vw = Vw + l*DD*DD; const float* vb = Vb + l*DD;
        const float* aw = Aw + l*DD*DD; const float* ab = Ab + l*DD;
        const float* bw = Bw + l*DD*DD; const float* bb = Bb + l*DD;
        const float* cw = Cw + l*DD*DD; const float* cb = Cb + l*DD;

        k_gemm<16,0><<<NN/16, DD>>>(ph, uw, ub, pUh, NN);
        k_gemm<16,0><<<NN/16, DD>>>(ph, vw, vb, pVh, NN);
        k_gemm<16,0><<<NN/16, DD>>>(ph, bw, bb, pBh, NN);
        k_gemm<16,0><<<NN/16, DD>>>(ph, cw, cb, pCh, NN);
        k_gemm<16,0><<<EE/16, DD>>>(pe, aw, ab, pet, EE);

        k_zero_f<<<(NN*DD+255)/256, 256>>>(pagg, NN*DD);
        k_edge<<<EE/8, DD>>>(src, dst);
        k_node_tmp<<<NN, DD>>>();

        k_zero_f<<<2, 256>>>(pst, 4*DD);
        k_colstats<256><<<(NN+255)/256, DD>>>(ptmp, NN, pst + 0*DD, pst + 1*DD);
        k_colstats<512><<<(EE+511)/512, DD>>>(pet, EE, pst + 2*DD, pst + 3*DD);
        k_bn_fin<<<1, DD>>>(pst + 0*DD, pst + 1*DD, h_g + l*DD, h_bt + l*DD,
                            (float)NN, psc + 0*DD, psh + 0*DD);
        k_bn_fin<<<1, DD>>>(pst + 2*DD, pst + 3*DD, e_g + l*DD, e_bt + l*DD,
                            (float)EE, psc + 1*DD, psh + 1*DD);

        k_apply<<<NN, DD>>>(ph, ptmp, psc + 0*DD, psh + 0*DD);
        k_apply<<<EE, DD>>>(pe, pet, psc + 1*DD, psh + 1*DD);
    }

    k_final<<<EE/4, DD>>>(f1w, f1b, f2w, f2b, f3w, f3b, out);
}

// round 3
// speedup vs baseline: 1.2535x; 1.2535x over previous
#include <cuda_runtime.h>
#include <math.h>

#define NN 20000
#define EE 320000
#define DD 128
#define LL 3
#define BN_EPS 1e-5f
#define NB (EE/32)      // 10000 edge blocks (32 edges each)
#define AST 36          // padded shared stride (144B, 16B-aligned rows)

// ---------------- scratch (device globals; no allocation) ----------------
__device__ float g_h [NN*DD];
__device__ float g_e [EE*DD];
__device__ float g_et[EE*DD];
__device__ float g_Uh[NN*DD];
__device__ float g_Vh[NN*DD];
__device__ float g_Bh[NN*DD];
__device__ float g_Ch[NN*DD];
__device__ float g_agg[NN*DD];
__device__ float g_tmp[NN*DD];
__device__ float g_cnt[NN];
__device__ int   g_cnti[NN];
__device__ float g_eps[2*DD*NB];   // edge BN partials: [d][blk] sum, [128+d][blk] sumsq
// stats: [0:128) sum_h, [128:256) sq_h, [256:384) sum_e, [384:512) sq_e
__device__ float g_stats[4*DD];
__device__ float g_scale[2*DD];    // [h | e]
__device__ float g_shift[2*DD];

// ---------------- helpers ----------------
__device__ __forceinline__ float sigm(float v){ return 1.f/(1.f+__expf(-v)); }
__device__ __forceinline__ float silu(float v){ return v*sigm(v); }

__device__ __forceinline__ unsigned long long pack2(float x, float y){
    unsigned long long r;
    asm("mov.b64 %0, {%1,%2};" : "=l"(r) : "f"(x), "f"(y));
    return r;
}
__device__ __forceinline__ void fma2(unsigned long long &d, unsigned long long a, unsigned long long b){
    asm("fma.rn.f32x2 %0, %1, %2, %0;" : "+l"(d) : "l"(a), "l"(b));
}
__device__ __forceinline__ void unpack2(unsigned long long v, float &x, float &y){
    asm("mov.b64 {%0,%1}, %2;" : "=f"(x), "=f"(y) : "l"(v));
}
__device__ __forceinline__ void lds2x2(unsigned int addr, unsigned long long &a, unsigned long long &b){
    asm volatile("ld.shared.v2.u64 {%0,%1}, [%2];" : "=l"(a), "=l"(b) : "r"(addr));
}

// FFMA2 GEMM core: 32 rows staged transposed in shared (stride AST), thread owns
// column tid; accumulates 16 packed row-pairs over K=128.
__device__ __forceinline__ void gemm2_core(unsigned int sbase, const float* __restrict__ W,
                                           int tid, unsigned long long acc[16]){
    #pragma unroll
    for (int j = 0; j < 16; j++) acc[j] = 0ull;
    #pragma unroll 2
    for (int k = 0; k < DD; k++){
        float w = W[k*DD + tid];
        unsigned long long w2 = pack2(w, w);
        unsigned int a = sbase + k*(AST*4);
        #pragma unroll
        for (int j = 0; j < 8; j++){
            unsigned long long p0, p1;
            lds2x2(a + j*16, p0, p1);
            fma2(acc[2*j],   p0, w2);
            fma2(acc[2*j+1], p1, w2);
        }
    }
}

// ---------------- small kernels ----------------
__global__ void k_zero_f4(float4* p, int n){
    int i = blockIdx.x*blockDim.x + threadIdx.x;
    if (i < n) p[i] = make_float4(0.f,0.f,0.f,0.f);
}
__global__ void k_zero_f(float* p, int n){
    int i = blockIdx.x*blockDim.x + threadIdx.x;
    if (i < n) p[i] = 0.f;
}
__global__ void k_zero_i(int* p, int n){
    int i = blockIdx.x*blockDim.x + threadIdx.x;
    if (i < n) p[i] = 0;
}
__global__ void k_count(const int* __restrict__ src){
    int i = blockIdx.x*blockDim.x + threadIdx.x;
    if (i < EE) atomicAdd(&g_cnti[src[i]], 1);
}
__global__ void k_cntf(){
    int i = blockIdx.x*blockDim.x + threadIdx.x;
    if (i < NN) g_cnt[i] = fmaxf((float)g_cnti[i], 1.f);
}
__global__ void k_init_h(const float* __restrict__ x,
                         const float* __restrict__ hw,
                         const float* __restrict__ hb){
    int n = blockIdx.x, d = threadIdx.x;
    float v = fmaf(x[n*2+0], hw[d], fmaf(x[n*2+1], hw[DD+d], hb[d]));
    g_h[n*DD+d] = silu(v);
}
__global__ void k_init_e(const float* __restrict__ ea,
                         const float* __restrict__ ew,
                         const float* __restrict__ eb){
    int e = blockIdx.x, d = threadIdx.x;
    float v = fmaf(ea[e], ew[d], eb[d]);
    g_e[e*DD+d] = silu(v);
}

// ---------------- node GEMM: out = A @ W + b, 32 rows/block ----------------
__global__ void k_gemm2(const float* __restrict__ A, const float* __restrict__ W,
                        const float* __restrict__ bias, float* __restrict__ out){
    __shared__ __align__(16) float AsT[DD*AST];
    const int tid = threadIdx.x;
    const int r0 = blockIdx.x * 32;
    #pragma unroll 8
    for (int r = 0; r < 32; r++) AsT[tid*AST + r] = A[(r0+r)*DD + tid];
    __syncthreads();
    unsigned int sbase = (unsigned int)__cvta_generic_to_shared(AsT);
    unsigned long long acc[16];
    gemm2_core(sbase, W, tid, acc);
    float b = bias[tid];
    #pragma unroll
    for (int j = 0; j < 16; j++){
        float v0, v1; unpack2(acc[j], v0, v1);
        out[(r0+2*j  )*DD + tid] = v0 + b;
        out[(r0+2*j+1)*DD + tid] = v1 + b;
    }
}

// ---------------- fused edge kernel (per layer) ----------------
// Computes et = e@Aw + ab + Bh[src] + Ch[dst], writes et, accumulates BN
// column partials, and (DO_MSG) scatters sigm(e)*Vh[dst] into agg.
template<int DO_MSG>
__global__ void k_edge_fused(const float* __restrict__ W, const float* __restrict__ bias,
                             const int* __restrict__ src, const int* __restrict__ dst){
    __shared__ __align__(16) float AsT[DD*AST];
    __shared__ int sh_s[32], sh_t[32];
    const int tid = threadIdx.x;
    const int blk = blockIdx.x;
    const int e0  = blk * 32;

    #pragma unroll 8
    for (int r = 0; r < 32; r++) AsT[tid*AST + r] = g_e[(e0+r)*DD + tid];
    if (tid < 32){ sh_s[tid] = src[e0+tid]; sh_t[tid] = dst[e0+tid]; }
    __syncthreads();

    unsigned int sbase = (unsigned int)__cvta_generic_to_shared(AsT);
    unsigned long long acc[16];
    gemm2_core(sbase, W, tid, acc);

    float vv[32];
    #pragma unroll
    for (int j = 0; j < 16; j++) unpack2(acc[j], vv[2*j], vv[2*j+1]);

    float b = bias[tid];
    float s = 0.f, q = 0.f;
    #pragma unroll 4
    for (int r = 0; r < 32; r++){
        int ss = sh_s[r], tt = sh_t[r];
        float et = vv[r] + b + g_Bh[ss*DD + tid] + g_Ch[tt*DD + tid];
        g_et[(e0+r)*DD + tid] = et;
        s += et;
        q = fmaf(et, et, q);
        if (DO_MSG){
            float ev = AsT[tid*AST + r];
            atomicAdd(&g_agg[ss*DD + tid], sigm(ev) * g_Vh[tt*DD + tid]);
        }
    }
    g_eps[tid*NB + blk]        = s;
    g_eps[(tid+DD)*NB + blk]   = q;
}

// reduce edge BN partials into g_stats[2*DD .. 4*DD)
__global__ void k_eps_reduce(float* __restrict__ pst){
    const int row = blockIdx.x;   // 0..255
    const float* p = g_eps + row*NB;
    float s = 0.f;
    for (int i = threadIdx.x; i < NB; i += 256) s += p[i];
    __shared__ float red[256];
    red[threadIdx.x] = s; __syncthreads();
    for (int o = 128; o > 0; o >>= 1){
        if (threadIdx.x < o) red[threadIdx.x] += red[threadIdx.x + o];
        __syncthreads();
    }
    if (threadIdx.x == 0){
        if (row < DD) pst[2*DD + row]        = red[0];
        else          pst[3*DD + (row-DD)]   = red[0];
    }
}

__global__ void k_node_tmp(){
    int n = blockIdx.x, d = threadIdx.x;
    g_tmp[n*DD + d] = g_Uh[n*DD + d] + g_agg[n*DD + d] / g_cnt[n];
}

template<int R>
__global__ void k_colstats(const float* __restrict__ X, int rows,
                           float* __restrict__ sum, float* __restrict__ sumsq){
    const int d = threadIdx.x;
    const int r0 = blockIdx.x * R;
    const int r1 = min(rows, r0 + R);
    float s = 0.f, q = 0.f;
    for (int r = r0; r < r1; r++){
        float v = X[r*DD + d];
        s += v;
        q = fmaf(v, v, q);
    }
    atomicAdd(&sum[d], s);
    atomicAdd(&sumsq[d], q);
}

__global__ void k_bn_fin(const float* __restrict__ sum, const float* __restrict__ sumsq,
                         const float* __restrict__ gamma, const float* __restrict__ beta,
                         float rows, float* __restrict__ scale, float* __restrict__ shift){
    int d = threadIdx.x;
    float m   = sum[d] / rows;
    float var = sumsq[d] / rows - m*m;
    float inv = rsqrtf(var + BN_EPS);
    float sc  = inv * gamma[d];
    scale[d] = sc;
    shift[d] = beta[d] - m*sc;
}

// base += silu(X*scale + shift), vectorized
__global__ void k_apply4(float4* __restrict__ base, const float4* __restrict__ X,
                         const float4* __restrict__ sc4, const float4* __restrict__ sh4, int n4){
    int i = blockIdx.x*blockDim.x + threadIdx.x;
    if (i >= n4) return;
    int c = i & 31;
    float4 x = X[i], s = sc4[c], h = sh4[c], b = base[i];
    b.x += silu(fmaf(x.x, s.x, h.x));
    b.y += silu(fmaf(x.y, s.y, h.y));
    b.z += silu(fmaf(x.z, s.z, h.z));
    b.w += silu(fmaf(x.w, s.w, h.w));
    base[i] = b;
}

// ---------------- fused final: apply(e,layer3) -> MLP -> sigmoid ----------------
__global__ void k_final(const float* __restrict__ f1w, const float* __restrict__ f1b,
                        const float* __restrict__ f2w, const float* __restrict__ f2b,
                        const float* __restrict__ f3w, const float* __restrict__ f3b,
                        const float* __restrict__ sc_, const float* __restrict__ sh_,
                        float* __restrict__ out){
    __shared__ __align__(16) float T0[DD*AST];
    __shared__ __align__(16) float T1[DD*AST];
    const int tid = threadIdx.x;
    const int e0  = blockIdx.x * 32;

    // fused BN-apply + residual: e_new = e + silu(et*sc+sh), stored transposed
    float sc = sc_[tid], sh = sh_[tid];
    #pragma unroll 8
    for (int r = 0; r < 32; r++){
        float et = g_et[(e0+r)*DD + tid];
        float ev = g_e [(e0+r)*DD + tid];
        T0[tid*AST + r] = ev + silu(fmaf(et, sc, sh));
    }
    __syncthreads();

    unsigned int b0 = (unsigned int)__cvta_generic_to_shared(T0);
    unsigned int b1 = (unsigned int)__cvta_generic_to_shared(T1);
    unsigned long long acc[16];

    // stage 1: T0 -> T1
    gemm2_core(b0, f1w, tid, acc);
    {
        float bb = f1b[tid];
        #pragma unroll
        for (int j = 0; j < 16; j++){
            float v0, v1; unpack2(acc[j], v0, v1);
            T1[tid*AST + 2*j  ] = silu(v0 + bb);
            T1[tid*AST + 2*j+1] = silu(v1 + bb);
        }
    }
    __syncthreads();

    // stage 2: T1 -> T0
    gemm2_core(b1, f2w, tid, acc);
    {
        float bb = f2b[tid];
        #pragma unroll
        for (int j = 0; j < 16; j++){
            float v0, v1; unpack2(acc[j], v0, v1);
            T0[tid*AST + 2*j  ] = silu(v0 + bb);
            T0[tid*AST + 2*j+1] = silu(v1 + bb);
        }
    }
    __syncthreads();

    // stage 3: scale by f3w, stage for per-edge reduce (reuse T1 as [32][128])
    float fw = f3w[tid];
    #pragma unroll 8
    for (int r = 0; r < 32; r++) T1[r*DD + tid] = T0[tid*AST + r] * fw;
    __syncthreads();

    int w = tid >> 5, lane = tid & 31;
    float b3 = f3b[0];
    #pragma unroll
    for (int i = 0; i < 8; i++){
        int r = w*8 + i;
        float v = T1[r*DD + lane] + T1[r*DD + lane+32] + T1[r*DD + lane+64] + T1[r*DD + lane+96];
        #pragma unroll
        for (int off = 16; off > 0; off >>= 1)
            v += __shfl_down_sync(0xffffffff, v, off);
        if (lane == 0) out[e0 + r] = sigm(v + b3);
    }
}

// ---------------- host orchestration ----------------
extern "C" void kernel_launch(void* const* d_in, const int* in_sizes, int n_in,
                              void* d_out, int out_size){
    const float* x    = (const float*)d_in[0];
    const float* ea   = (const float*)d_in[1];
    const int*   eidx = (const int*)  d_in[2];
    const float* hp_w = (const float*)d_in[3];
    const float* hp_b = (const float*)d_in[4];
    const float* ep_w = (const float*)d_in[5];
    const float* ep_b = (const float*)d_in[6];
    const float* Uw   = (const float*)d_in[7];
    const float* Ub   = (const float*)d_in[8];
    const float* Vw   = (const float*)d_in[9];
    const float* Vb   = (const float*)d_in[10];
    const float* Aw   = (const float*)d_in[11];
    const float* Ab   = (const float*)d_in[12];
    const float* Bw   = (const float*)d_in[13];
    const float* Bb   = (const float*)d_in[14];
    const float* Cw   = (const float*)d_in[15];
    const float* Cb   = (const float*)d_in[16];
    const float* h_g  = (const float*)d_in[17];
    const float* h_bt = (const float*)d_in[18];
    const float* e_g  = (const float*)d_in[19];
    const float* e_bt = (const float*)d_in[20];
    const float* f1w  = (const float*)d_in[21];
    const float* f1b  = (const float*)d_in[22];
    const float* f2w  = (const float*)d_in[23];
    const float* f2b  = (const float*)d_in[24];
    const float* f3w  = (const float*)d_in[25];
    const float* f3b  = (const float*)d_in[26];
    float* out = (float*)d_out;

    const int* src = eidx;        // edge_index[0]: scatter target
    const int* dst = eidx + EE;   // edge_index[1]: gather source

    void* p;
    cudaGetSymbolAddress(&p, g_h);    float* ph    = (float*)p;
    cudaGetSymbolAddress(&p, g_e);    float* pe    = (float*)p;
    cudaGetSymbolAddress(&p, g_et);   float* pet   = (float*)p;
    cudaGetSymbolAddress(&p, g_Uh);   float* pUh   = (float*)p;
    cudaGetSymbolAddress(&p, g_Vh);   float* pVh   = (float*)p;
    cudaGetSymbolAddress(&p, g_Bh);   float* pBh   = (float*)p;
    cudaGetSymbolAddress(&p, g_Ch);   float* pCh   = (float*)p;
    cudaGetSymbolAddress(&p, g_agg);  float* pagg  = (float*)p;
    cudaGetSymbolAddress(&p, g_tmp);  float* ptmp  = (float*)p;
    cudaGetSymbolAddress(&p, g_cnti); int*   pcnti = (int*)p;
    cudaGetSymbolAddress(&p, g_stats);float* pst   = (float*)p;
    cudaGetSymbolAddress(&p, g_scale);float* psc   = (float*)p;
    cudaGetSymbolAddress(&p, g_shift);float* psh   = (float*)p;

    // input projections
    k_init_h<<<NN, DD>>>(x, hp_w, hp_b);
    k_init_e<<<EE, DD>>>(ea, ep_w, ep_b);

    // per-node counts
    k_zero_i<<<(NN+255)/256, 256>>>(pcnti, NN);
    k_count<<<(EE+255)/256, 256>>>(src);
    k_cntf<<<(NN+255)/256, 256>>>();

    for (int l = 0; l < LL; l++){
        const bool last = (l == LL-1);
        const float* uw = Uw + l*DD*DD; const float* ub = Ub + l*DD;
        const float* vw = Vw + l*DD*DD; const float* vb = Vb + l*DD;
        const float* aw = Aw + l*DD*DD; const float* ab = Ab + l*DD;
        const float* bw = Bw + l*DD*DD; const float* bb = Bb + l*DD;
        const float* cw = Cw + l*DD*DD; const float* cb = Cb + l*DD;

        // node GEMMs (h is never updated after the last layer's e-update)
        if (!last){
            k_gemm2<<<NN/32, DD>>>(ph, uw, ub, pUh);
            k_gemm2<<<NN/32, DD>>>(ph, vw, vb, pVh);
        }
        k_gemm2<<<NN/32, DD>>>(ph, bw, bb, pBh);
        k_gemm2<<<NN/32, DD>>>(ph, cw, cb, pCh);

        if (!last){
            k_zero_f4<<<(NN*DD/4+255)/256, 256>>>((float4*)pagg, NN*DD/4);
            k_edge_fused<1><<<NB, DD>>>(aw, ab, src, dst);
        } else {
            k_edge_fused<0><<<NB, DD>>>(aw, ab, src, dst);
        }

        k_zero_f<<<2, 256>>>(pst, 4*DD);
        k_eps_reduce<<<2*DD, 256>>>(pst);

        if (!last){
            k_node_tmp<<<NN, DD>>>();
            k_colstats<256><<<(NN+255)/256, DD>>>(ptmp, NN, pst + 0*DD, pst + 1*DD);
            k_bn_fin<<<1, DD>>>(pst + 0*DD, pst + 1*DD, h_g + l*DD, h_bt + l*DD,
                                (float)NN, psc + 0*DD, psh + 0*DD);
        }
        k_bn_fin<<<1, DD>>>(pst + 2*DD, pst + 3*DD, e_g + l*DD, e_bt + l*DD,
                            (float)EE, psc + 1*DD, psh + 1*DD);

        if (!last){
            k_apply4<<<(NN*DD/4+255)/256, 256>>>((float4*)ph, (const float4*)ptmp,
                                                 (const float4*)(psc+0*DD), (const float4*)(psh+0*DD), NN*DD/4);
            k_apply4<<<(EE*DD/4+255)/256, 256>>>((float4*)pe, (const float4*)pet,
                                                 (const float4*)(psc+1*DD), (const float4*)(psh+1*DD), EE*DD/4);
        }
    }

    // last layer e-apply fused into final MLP
    k_final<<<NB, DD>>>(f1w, f1b, f2w, f2b, f3w, f3b, psc + 1*DD, psh + 1*DD, out);
}